// round 1
// baseline (speedup 1.0000x reference)
#include <cuda_runtime.h>
#include <math.h>

// Problem constants
#define NB      4
#define CIN     512
#define HH      64
#define WW      64
#define HW      4096          // 64*64
#define QKVCH   1536
#define NGROUP  192           // PW groups (per qkv buffer view)
#define NHEAD   128           // 3072 concat channels / 24
#define ATTNCH  1024          // 128 heads * 8
#define EPSV    1e-5f
#define BNEPS   1e-5f

// Scratch (static device globals; runtime alloc is forbidden)
__device__ float g_qkv [(size_t)NB * QKVCH * HW];   // qkv = x @ w_qkv
__device__ float g_agg [(size_t)NB * QKVCH * HW];   // pw(dw(qkv))
__device__ float g_attn[(size_t)NB * ATTNCH * HW];  // attention output

// ---------------------------------------------------------------------------
// Generic GEMM over NCHW activations:
//   C[b][o][p] = sum_c A[b][c][p] * W[o][c]      (p = flattened H*W)
// Tile: 128 outputs x 128 pixels x K-tile 8, 256 threads, 8x8 per thread.
// Optional fused BN epilogue.
// ---------------------------------------------------------------------------
template <bool BN>
__global__ __launch_bounds__(256)
void gemm_ncp_kernel(const float* __restrict__ A,
                     const float* __restrict__ W,
                     float* __restrict__ C, int K,
                     const float* __restrict__ bn_gamma,
                     const float* __restrict__ bn_beta,
                     const float* __restrict__ bn_mean,
                     const float* __restrict__ bn_var)
{
    const int b  = blockIdx.z;
    const int p0 = blockIdx.x * 128;
    const int o0 = blockIdx.y * 128;
    const int N  = gridDim.y * 128;

    const float* Ab = A + (size_t)b * K * HW;

    __shared__ float As[8][128];
    __shared__ float Ws[8][132];   // padded: conflict-free writes, 16B-aligned rows

    const int t  = threadIdx.x;
    const int tx = t & 15;         // pixel sub-tile
    const int ty = t >> 4;         // output sub-tile

    float acc[8][8];
#pragma unroll
    for (int i = 0; i < 8; i++)
#pragma unroll
        for (int j = 0; j < 8; j++) acc[i][j] = 0.f;

    for (int kk = 0; kk < K; kk += 8) {
        // Stage A tile: 8 x 128, coalesced along pixels
#pragma unroll
        for (int i = 0; i < 4; i++) {
            int idx = t + i * 256;
            int r = idx >> 7, c = idx & 127;
            As[r][c] = Ab[(size_t)(kk + r) * HW + p0 + c];
        }
        // Stage W tile transposed: Ws[k][o] <- W[o0+o][kk+k]
#pragma unroll
        for (int i = 0; i < 4; i++) {
            int idx = t + i * 256;
            int c = idx & 7, o = idx >> 3;
            Ws[c][o] = W[(size_t)(o0 + o) * K + kk + c];
        }
        __syncthreads();

#pragma unroll
        for (int k = 0; k < 8; k++) {
            float4 w0 = *(const float4*)&Ws[k][ty * 8];
            float4 w1 = *(const float4*)&Ws[k][ty * 8 + 4];
            float4 a0 = *(const float4*)&As[k][tx * 8];
            float4 a1 = *(const float4*)&As[k][tx * 8 + 4];
            float wr[8] = {w0.x, w0.y, w0.z, w0.w, w1.x, w1.y, w1.z, w1.w};
            float ar[8] = {a0.x, a0.y, a0.z, a0.w, a1.x, a1.y, a1.z, a1.w};
#pragma unroll
            for (int i = 0; i < 8; i++)
#pragma unroll
                for (int j = 0; j < 8; j++)
                    acc[i][j] = fmaf(wr[i], ar[j], acc[i][j]);
        }
        __syncthreads();
    }

    float* Cb = C + (size_t)b * N * HW;
#pragma unroll
    for (int i = 0; i < 8; i++) {
        int o = o0 + ty * 8 + i;
        float s = 1.f, bi = 0.f;
        if (BN) {
            float inv = bn_gamma[o] / sqrtf(bn_var[o] + BNEPS);
            s  = inv;
            bi = bn_beta[o] - bn_mean[o] * inv;
        }
        float4 v0, v1;
        v0.x = acc[i][0] * s + bi;  v0.y = acc[i][1] * s + bi;
        v0.z = acc[i][2] * s + bi;  v0.w = acc[i][3] * s + bi;
        v1.x = acc[i][4] * s + bi;  v1.y = acc[i][5] * s + bi;
        v1.z = acc[i][6] * s + bi;  v1.w = acc[i][7] * s + bi;
        *(float4*)&Cb[(size_t)o * HW + p0 + tx * 8]     = v0;
        *(float4*)&Cb[(size_t)o * HW + p0 + tx * 8 + 4] = v1;
    }
}

// ---------------------------------------------------------------------------
// Fused depthwise 5x5 conv (pad 2) + grouped 8x8 pointwise mix.
// One block = one (batch, group, 8-row tile). dw values stay in registers,
// pointwise mix applied immediately.
// ---------------------------------------------------------------------------
__global__ __launch_bounds__(256)
void dwpw_kernel(const float* __restrict__ w_dw,
                 const float* __restrict__ w_pw)
{
    const int TR = 8;
    const int b  = blockIdx.z;
    const int g  = blockIdx.y;
    const int r0 = blockIdx.x * TR;
    const int t  = threadIdx.x;

    __shared__ float sin_[8][TR + 4][68];  // 8 ch x (rows+halo) x (cols+halo)
    __shared__ float swdw[8][25];
    __shared__ float swpw[64];

    const float* src = g_qkv + ((size_t)b * QKVCH + g * 8) * HW;
    float*       dst = g_agg + ((size_t)b * QKVCH + g * 8) * HW;

    if (t < 200) swdw[t / 25][t % 25] = w_dw[(size_t)(g * 8 + t / 25) * 25 + (t % 25)];
    if (t < 64)  swpw[t] = w_pw[(size_t)g * 64 + t];

    // Load input tile with halo (zero-padded): 8 * 12 * 68 = 6528 elements
    for (int idx = t; idx < 8 * (TR + 4) * 68; idx += 256) {
        int i   = idx / ((TR + 4) * 68);
        int rem = idx % ((TR + 4) * 68);
        int rr  = rem / 68, cc = rem % 68;
        int gr  = r0 + rr - 2, gc = cc - 2;
        float v = 0.f;
        if (gr >= 0 && gr < HH && gc >= 0 && gc < WW)
            v = src[(size_t)i * HW + gr * WW + gc];
        sin_[i][rr][cc] = v;
    }
    __syncthreads();

    for (int px = t; px < TR * WW; px += 256) {
        int rr = px >> 6, cc = px & 63;
        float dwv[8];
#pragma unroll
        for (int i = 0; i < 8; i++) {
            float s = 0.f;
#pragma unroll
            for (int dy = 0; dy < 5; dy++)
#pragma unroll
                for (int dx = 0; dx < 5; dx++)
                    s = fmaf(sin_[i][rr + dy][cc + dx], swdw[i][dy * 5 + dx], s);
            dwv[i] = s;
        }
        int pout = (r0 + rr) * WW + cc;
#pragma unroll
        for (int o = 0; o < 8; o++) {
            float s = 0.f;
#pragma unroll
            for (int i = 0; i < 8; i++) s = fmaf(dwv[i], swpw[o * 8 + i], s);
            dst[(size_t)o * HW + pout] = s;
        }
    }
}

// ---------------------------------------------------------------------------
// Linear attention per (batch, head).
// Head h < 64 sources from g_qkv (channels h*24..), h >= 64 from g_agg.
// Within the 24-channel block: q=0..7 (relu), k=8..15 (relu), v=16..23,
// v padded with implicit 1.0 (column 8).
// Phase A: KV[8][9] reduction over 4096 pixels. Phase B: out = qKV, normalize.
// ---------------------------------------------------------------------------
__global__ __launch_bounds__(256)
void attn_kernel()
{
    const int b = blockIdx.y;
    const int h = blockIdx.x;
    const int t = threadIdx.x;

    const float* base = (h < 64)
        ? g_qkv + ((size_t)b * QKVCH + h * 24) * HW
        : g_agg + ((size_t)b * QKVCH + (h - 64) * 24) * HW;

    float kv[72];
#pragma unroll
    for (int i = 0; i < 72; i++) kv[i] = 0.f;

    for (int p = t; p < HW; p += 256) {
        float kd[8], ve[8];
#pragma unroll
        for (int d = 0; d < 8; d++) kd[d] = fmaxf(base[(size_t)(8 + d) * HW + p], 0.f);
#pragma unroll
        for (int e = 0; e < 8; e++) ve[e] = base[(size_t)(16 + e) * HW + p];
#pragma unroll
        for (int d = 0; d < 8; d++) {
#pragma unroll
            for (int e = 0; e < 8; e++) kv[d * 9 + e] = fmaf(kd[d], ve[e], kv[d * 9 + e]);
            kv[d * 9 + 8] += kd[d];
        }
    }

    // Reduce 72 partial KV values across the block
    __shared__ float red[8][72];
    __shared__ float kvf[72];
#pragma unroll
    for (int i = 0; i < 72; i++) {
        float v = kv[i];
        v += __shfl_xor_sync(0xffffffffu, v, 16);
        v += __shfl_xor_sync(0xffffffffu, v, 8);
        v += __shfl_xor_sync(0xffffffffu, v, 4);
        v += __shfl_xor_sync(0xffffffffu, v, 2);
        v += __shfl_xor_sync(0xffffffffu, v, 1);
        kv[i] = v;
    }
    const int lane = t & 31, wid = t >> 5;
    if (lane == 0) {
#pragma unroll
        for (int i = 0; i < 72; i++) red[wid][i] = kv[i];
    }
    __syncthreads();
    if (t < 72) {
        float s = 0.f;
#pragma unroll
        for (int w = 0; w < 8; w++) s += red[w][t];
        kvf[t] = s;
    }
    __syncthreads();

    float* dst = g_attn + ((size_t)b * ATTNCH + h * 8) * HW;
    for (int p = t; p < HW; p += 256) {
        float qd[8];
#pragma unroll
        for (int d = 0; d < 8; d++) qd[d] = fmaxf(base[(size_t)d * HW + p], 0.f);
        float num[9];
#pragma unroll
        for (int e = 0; e < 9; e++) {
            float s = 0.f;
#pragma unroll
            for (int d = 0; d < 8; d++) s = fmaf(qd[d], kvf[d * 9 + e], s);
            num[e] = s;
        }
        float inv = 1.f / (num[8] + EPSV);
#pragma unroll
        for (int e = 0; e < 8; e++) dst[(size_t)e * HW + p] = num[e] * inv;
    }
}

// ---------------------------------------------------------------------------
extern "C" void kernel_launch(void* const* d_in, const int* in_sizes, int n_in,
                              void* d_out, int out_size)
{
    const float* x       = (const float*)d_in[0];
    const float* w_qkv   = (const float*)d_in[1];
    const float* w_dw    = (const float*)d_in[2];
    const float* w_pw    = (const float*)d_in[3];
    const float* w_proj  = (const float*)d_in[4];
    const float* bn_g    = (const float*)d_in[5];
    const float* bn_b    = (const float*)d_in[6];
    const float* bn_m    = (const float*)d_in[7];
    const float* bn_v    = (const float*)d_in[8];
    float* out = (float*)d_out;

    float *qkv_p, *agg_p, *attn_p;
    cudaGetSymbolAddress((void**)&qkv_p,  g_qkv);
    cudaGetSymbolAddress((void**)&agg_p,  g_agg);
    cudaGetSymbolAddress((void**)&attn_p, g_attn);

    // 1) qkv = x @ w_qkv   (K=512, N=1536)
    gemm_ncp_kernel<false><<<dim3(HW / 128, QKVCH / 128, NB), 256>>>(
        x, w_qkv, qkv_p, CIN, nullptr, nullptr, nullptr, nullptr);

    // 2) depthwise 5x5 + grouped pointwise 8x8
    dwpw_kernel<<<dim3(HH / 8, NGROUP, NB), 256>>>(w_dw, w_pw);

    // 3) linear attention (128 heads)
    attn_kernel<<<dim3(NHEAD, NB), 256>>>();

    // 4) proj GEMM (K=1024, N=512) + BN affine
    gemm_ncp_kernel<true><<<dim3(HW / 128, CIN / 128, NB), 256>>>(
        attn_p, w_proj, out, ATTNCH, bn_g, bn_b, bn_m, bn_v);
}

// round 5
// speedup vs baseline: 1.7907x; 1.7907x over previous
#include <cuda_runtime.h>
#include <cuda_bf16.h>
#include <math.h>
#include <stdint.h>

// Problem constants
#define NB      4
#define CIN     512
#define HH      64
#define WW      64
#define HW      4096
#define QKVCH   1536
#define NGROUP  192
#define NHEAD   128
#define ATTNCH  1024
#define EPSV    1e-5f
#define BNEPS   1e-5f

// Scratch
__device__ float g_qkv [(size_t)NB * QKVCH * HW];
__device__ float g_agg [(size_t)NB * QKVCH * HW];
__device__ float g_attn[(size_t)NB * ATTNCH * HW];

// ===========================================================================
// Helpers: bf16 2-term split + mma.sync (sm_80+ HMMA path; works on sm_100)
// ===========================================================================
__device__ __forceinline__ void split_bf16(float x, uint16_t& h, uint16_t& l) {
    __nv_bfloat16 hb = __float2bfloat16_rn(x);
    float r = x - __bfloat162float(hb);
    __nv_bfloat16 lb = __float2bfloat16_rn(r);
    h = __nv_bfloat16_raw(hb).x;
    l = __nv_bfloat16_raw(lb).x;
}
__device__ __forceinline__ uint32_t pack2(uint16_t lo16, uint16_t hi16) {
    return (uint32_t)lo16 | ((uint32_t)hi16 << 16);
}
__device__ __forceinline__ void mma_bf16(float d[4], const uint32_t a[4],
                                         uint32_t b0, uint32_t b1) {
    asm volatile(
        "mma.sync.aligned.m16n8k16.row.col.f32.bf16.bf16.f32 "
        "{%0,%1,%2,%3}, {%4,%5,%6,%7}, {%8,%9}, {%0,%1,%2,%3};\n"
        : "+f"(d[0]), "+f"(d[1]), "+f"(d[2]), "+f"(d[3])
        : "r"(a[0]), "r"(a[1]), "r"(a[2]), "r"(a[3]), "r"(b0), "r"(b1));
}

// ===========================================================================
// GEMM:  C[b][o][p] = sum_c W[o][c] * Act[b][c][p]
// Block tile: 128 o x 128 p, K-tile 32. 8 warps (4 m x 2 n), warp 32o x 64p.
// A = W (row-major, k contig).  B = Act staged as bf16x2 k-pair words [kp][n].
// 2-term bf16 split: hi*hi + hi*lo + lo*hi  (3 MMAs / fragment pair).
// ===========================================================================
#define A_STRIDE 20    // words per A row (16 kp + pad) -> conflict-free frags
#define B_STRIDE 136   // words per B kp-row (128 n + pad) -> conflict-free

template <bool BN>
__global__ __launch_bounds__(256, 2)
void mma_gemm_kernel(const float* __restrict__ Act,
                     const float* __restrict__ Wt,
                     float* __restrict__ C, int K, int Ochan,
                     const float* __restrict__ bn_gamma,
                     const float* __restrict__ bn_beta,
                     const float* __restrict__ bn_mean,
                     const float* __restrict__ bn_var)
{
    __shared__ uint32_t sAh[128 * A_STRIDE];
    __shared__ uint32_t sAl[128 * A_STRIDE];
    __shared__ uint32_t sBh[16 * B_STRIDE];
    __shared__ uint32_t sBl[16 * B_STRIDE];

    const int t = threadIdx.x, lane = t & 31, wid = t >> 5;
    const int wm = wid & 3;        // m (output-channel) warp coord
    const int wn = wid >> 2;       // n (pixel) warp coord
    const int bx = blockIdx.x;
    const int b  = bx >> 5;
    const int p0 = (bx & 31) * 128;
    const int o0 = blockIdx.y * 128;

    const float* Ab = Act + (size_t)b * K * HW;

    float acc[2][8][4];
#pragma unroll
    for (int i = 0; i < 2; i++)
#pragma unroll
        for (int j = 0; j < 8; j++)
#pragma unroll
            for (int e = 0; e < 4; e++) acc[i][j][e] = 0.f;

    for (int kk = 0; kk < K; kk += 32) {
        // ---- stage A = W tile [128 o][32 c], split into hi/lo bf16x2 words ----
#pragma unroll
        for (int i = 0; i < 4; i++) {
            int idx = t + i * 256;          // 0..1023
            int o = idx >> 3, ch = idx & 7; // 8 float4 per row
            float4 v = *(const float4*)&Wt[(size_t)(o0 + o) * K + kk + ch * 4];
            uint16_t h0, l0, h1, l1, h2, l2, h3, l3;
            split_bf16(v.x, h0, l0); split_bf16(v.y, h1, l1);
            split_bf16(v.z, h2, l2); split_bf16(v.w, h3, l3);
            int sw = o * A_STRIDE + ch * 2;
            sAh[sw] = pack2(h0, h1); sAh[sw + 1] = pack2(h2, h3);
            sAl[sw] = pack2(l0, l1); sAl[sw + 1] = pack2(l2, l3);
        }
        // ---- stage B = Act tile [32 c][128 p] as k-pair words [kp][n] ----
#pragma unroll
        for (int i = 0; i < 2; i++) {
            int idx = t + i * 256;          // 0..511
            int kp = idx >> 5, n0 = (idx & 31) * 4;
            const float* r = Ab + (size_t)(kk + 2 * kp) * HW + p0 + n0;
            float4 va = *(const float4*)r;           // k = 2kp
            float4 vb = *(const float4*)(r + HW);    // k = 2kp+1
            uint16_t ha[4], la[4], hb[4], lb[4];
            split_bf16(va.x, ha[0], la[0]); split_bf16(va.y, ha[1], la[1]);
            split_bf16(va.z, ha[2], la[2]); split_bf16(va.w, ha[3], la[3]);
            split_bf16(vb.x, hb[0], lb[0]); split_bf16(vb.y, hb[1], lb[1]);
            split_bf16(vb.z, hb[2], lb[2]); split_bf16(vb.w, hb[3], lb[3]);
            uint4 hv = make_uint4(pack2(ha[0], hb[0]), pack2(ha[1], hb[1]),
                                  pack2(ha[2], hb[2]), pack2(ha[3], hb[3]));
            uint4 lv = make_uint4(pack2(la[0], lb[0]), pack2(la[1], lb[1]),
                                  pack2(la[2], lb[2]), pack2(la[3], lb[3]));
            *(uint4*)&sBh[kp * B_STRIDE + n0] = hv;
            *(uint4*)&sBl[kp * B_STRIDE + n0] = lv;
        }
        __syncthreads();

        // ---- compute: 2 k16-steps ----
#pragma unroll
        for (int s = 0; s < 2; s++) {
            uint32_t ah[2][4], al[2][4];
            int baseA = (wm * 32 + (lane >> 2)) * A_STRIDE + s * 8 + (lane & 3);
#pragma unroll
            for (int i = 0; i < 2; i++) {
                int ba = baseA + i * 16 * A_STRIDE;
                ah[i][0] = sAh[ba];
                ah[i][1] = sAh[ba + 8 * A_STRIDE];
                ah[i][2] = sAh[ba + 4];
                ah[i][3] = sAh[ba + 8 * A_STRIDE + 4];
                al[i][0] = sAl[ba];
                al[i][1] = sAl[ba + 8 * A_STRIDE];
                al[i][2] = sAl[ba + 4];
                al[i][3] = sAl[ba + 8 * A_STRIDE + 4];
            }
            int baseB = (s * 8 + (lane & 3)) * B_STRIDE + wn * 64 + (lane >> 2);
#pragma unroll
            for (int j = 0; j < 8; j++) {
                uint32_t bh0 = sBh[baseB + 8 * j];
                uint32_t bh1 = sBh[baseB + 4 * B_STRIDE + 8 * j];
                uint32_t bl0 = sBl[baseB + 8 * j];
                uint32_t bl1 = sBl[baseB + 4 * B_STRIDE + 8 * j];
#pragma unroll
                for (int i = 0; i < 2; i++) {
                    mma_bf16(acc[i][j], ah[i], bh0, bh1);
                    mma_bf16(acc[i][j], ah[i], bl0, bl1);
                    mma_bf16(acc[i][j], al[i], bh0, bh1);
                }
            }
        }
        __syncthreads();
    }

    // ---- epilogue (optional fused BN affine) ----
    const int orow = o0 + wm * 32 + (lane >> 2);
    float scl[4], bia[4];
#pragma unroll
    for (int r = 0; r < 4; r++) {
        if (BN) {
            int o = orow + 8 * r;
            float inv = bn_gamma[o] * rsqrtf(bn_var[o] + BNEPS);
            scl[r] = inv;
            bia[r] = bn_beta[o] - bn_mean[o] * inv;
        } else { scl[r] = 1.f; bia[r] = 0.f; }
    }
    float* Cb = C + (size_t)b * Ochan * HW;
    const int pbase = p0 + wn * 64 + (lane & 3) * 2;
#pragma unroll
    for (int i = 0; i < 2; i++) {
        int oA = orow + 16 * i;
        int r0 = 2 * i;
#pragma unroll
        for (int j = 0; j < 8; j++) {
            int p = pbase + 8 * j;
            float2 v0, v1;
            v0.x = acc[i][j][0] * scl[r0] + bia[r0];
            v0.y = acc[i][j][1] * scl[r0] + bia[r0];
            v1.x = acc[i][j][2] * scl[r0 + 1] + bia[r0 + 1];
            v1.y = acc[i][j][3] * scl[r0 + 1] + bia[r0 + 1];
            *(float2*)&Cb[(size_t)oA * HW + p]       = v0;
            *(float2*)&Cb[(size_t)(oA + 8) * HW + p] = v1;
        }
    }
}

// ---------------------------------------------------------------------------
// Fused depthwise 5x5 conv (pad 2) + grouped 8x8 pointwise mix.
// ---------------------------------------------------------------------------
__global__ __launch_bounds__(256)
void dwpw_kernel(const float* __restrict__ w_dw,
                 const float* __restrict__ w_pw)
{
    const int TR = 8;
    const int b  = blockIdx.z;
    const int g  = blockIdx.y;
    const int r0 = blockIdx.x * TR;
    const int t  = threadIdx.x;

    __shared__ float sin_[8][TR + 4][68];
    __shared__ float swdw[8][25];
    __shared__ float swpw[64];

    const float* src = g_qkv + ((size_t)b * QKVCH + g * 8) * HW;
    float*       dst = g_agg + ((size_t)b * QKVCH + g * 8) * HW;

    if (t < 200) swdw[t / 25][t % 25] = w_dw[(size_t)(g * 8 + t / 25) * 25 + (t % 25)];
    if (t < 64)  swpw[t] = w_pw[(size_t)g * 64 + t];

    for (int idx = t; idx < 8 * (TR + 4) * 68; idx += 256) {
        int i   = idx / ((TR + 4) * 68);
        int rem = idx % ((TR + 4) * 68);
        int rr  = rem / 68, cc = rem % 68;
        int gr  = r0 + rr - 2, gc = cc - 2;
        float v = 0.f;
        if (gr >= 0 && gr < HH && gc >= 0 && gc < WW)
            v = src[(size_t)i * HW + gr * WW + gc];
        sin_[i][rr][cc] = v;
    }
    __syncthreads();

    for (int px = t; px < TR * WW; px += 256) {
        int rr = px >> 6, cc = px & 63;
        float dwv[8];
#pragma unroll
        for (int i = 0; i < 8; i++) {
            float s = 0.f;
#pragma unroll
            for (int dy = 0; dy < 5; dy++)
#pragma unroll
                for (int dx = 0; dx < 5; dx++)
                    s = fmaf(sin_[i][rr + dy][cc + dx], swdw[i][dy * 5 + dx], s);
            dwv[i] = s;
        }
        int pout = (r0 + rr) * WW + cc;
#pragma unroll
        for (int o = 0; o < 8; o++) {
            float s = 0.f;
#pragma unroll
            for (int i = 0; i < 8; i++) s = fmaf(dwv[i], swpw[o * 8 + i], s);
            dst[(size_t)o * HW + pout] = s;
        }
    }
}

// ---------------------------------------------------------------------------
// Linear attention per (batch, head).
// ---------------------------------------------------------------------------
__global__ __launch_bounds__(256)
void attn_kernel()
{
    const int b = blockIdx.y;
    const int h = blockIdx.x;
    const int t = threadIdx.x;

    const float* base = (h < 64)
        ? g_qkv + ((size_t)b * QKVCH + h * 24) * HW
        : g_agg + ((size_t)b * QKVCH + (h - 64) * 24) * HW;

    float kv[72];
#pragma unroll
    for (int i = 0; i < 72; i++) kv[i] = 0.f;

    for (int p = t; p < HW; p += 256) {
        float kd[8], ve[8];
#pragma unroll
        for (int d = 0; d < 8; d++) kd[d] = fmaxf(base[(size_t)(8 + d) * HW + p], 0.f);
#pragma unroll
        for (int e = 0; e < 8; e++) ve[e] = base[(size_t)(16 + e) * HW + p];
#pragma unroll
        for (int d = 0; d < 8; d++) {
#pragma unroll
            for (int e = 0; e < 8; e++) kv[d * 9 + e] = fmaf(kd[d], ve[e], kv[d * 9 + e]);
            kv[d * 9 + 8] += kd[d];
        }
    }

    __shared__ float red[8][72];
    __shared__ float kvf[72];
#pragma unroll
    for (int i = 0; i < 72; i++) {
        float v = kv[i];
        v += __shfl_xor_sync(0xffffffffu, v, 16);
        v += __shfl_xor_sync(0xffffffffu, v, 8);
        v += __shfl_xor_sync(0xffffffffu, v, 4);
        v += __shfl_xor_sync(0xffffffffu, v, 2);
        v += __shfl_xor_sync(0xffffffffu, v, 1);
        kv[i] = v;
    }
    const int lane = t & 31, wid = t >> 5;
    if (lane == 0) {
#pragma unroll
        for (int i = 0; i < 72; i++) red[wid][i] = kv[i];
    }
    __syncthreads();
    if (t < 72) {
        float s = 0.f;
#pragma unroll
        for (int w = 0; w < 8; w++) s += red[w][t];
        kvf[t] = s;
    }
    __syncthreads();

    float* dst = g_attn + ((size_t)b * ATTNCH + h * 8) * HW;
    for (int p = t; p < HW; p += 256) {
        float qd[8];
#pragma unroll
        for (int d = 0; d < 8; d++) qd[d] = fmaxf(base[(size_t)d * HW + p], 0.f);
        float num[9];
#pragma unroll
        for (int e = 0; e < 9; e++) {
            float s = 0.f;
#pragma unroll
            for (int d = 0; d < 8; d++) s = fmaf(qd[d], kvf[d * 9 + e], s);
            num[e] = s;
        }
        float inv = 1.f / (num[8] + EPSV);
#pragma unroll
        for (int e = 0; e < 8; e++) dst[(size_t)e * HW + p] = num[e] * inv;
    }
}

// ---------------------------------------------------------------------------
extern "C" void kernel_launch(void* const* d_in, const int* in_sizes, int n_in,
                              void* d_out, int out_size)
{
    const float* x       = (const float*)d_in[0];
    const float* w_qkv   = (const float*)d_in[1];
    const float* w_dw    = (const float*)d_in[2];
    const float* w_pw    = (const float*)d_in[3];
    const float* w_proj  = (const float*)d_in[4];
    const float* bn_g    = (const float*)d_in[5];
    const float* bn_b    = (const float*)d_in[6];
    const float* bn_m    = (const float*)d_in[7];
    const float* bn_v    = (const float*)d_in[8];
    float* out = (float*)d_out;

    float *qkv_p, *agg_p, *attn_p;
    cudaGetSymbolAddress((void**)&qkv_p,  g_qkv);
    cudaGetSymbolAddress((void**)&agg_p,  g_agg);
    cudaGetSymbolAddress((void**)&attn_p, g_attn);

    // 1) qkv = x @ w_qkv   (K=512, O=1536)
    mma_gemm_kernel<false><<<dim3(128, QKVCH / 128), 256>>>(
        x, w_qkv, qkv_p, CIN, QKVCH, nullptr, nullptr, nullptr, nullptr);

    // 2) depthwise 5x5 + grouped pointwise 8x8
    dwpw_kernel<<<dim3(HH / 8, NGROUP, NB), 256>>>(w_dw, w_pw);

    // 3) linear attention (128 heads)
    attn_kernel<<<dim3(NHEAD, NB), 256>>>();

    // 4) proj GEMM (K=1024, O=512) + BN affine
    mma_gemm_kernel<true><<<dim3(128, CIN / 128), 256>>>(
        attn_p, w_proj, out, ATTNCH, CIN, bn_g, bn_b, bn_m, bn_v);
}

// round 7
// speedup vs baseline: 1.8055x; 1.0083x over previous
#include <cuda_runtime.h>
#include <cuda_bf16.h>
#include <math.h>
#include <stdint.h>

// Problem constants
#define NB      4
#define CIN     512
#define HH      64
#define WW      64
#define HW      4096
#define QKVCH   1536
#define NGROUP  192
#define NHEAD   128
#define ATTNCH  1024
#define EPSV    1e-5f
#define BNEPS   1e-5f

// Scratch: fp32 intermediates
__device__ float g_qkv [(size_t)NB * QKVCH * HW];
__device__ float g_agg [(size_t)NB * QKVCH * HW];
// Pre-split packed k-pair bf16 buffers (word = bf16(ch 2kp) | bf16(ch 2kp+1)<<16)
__device__ uint32_t g_xh   [(size_t)NB * (CIN / 2) * HW];
__device__ uint32_t g_xl   [(size_t)NB * (CIN / 2) * HW];
__device__ uint32_t g_atth [(size_t)NB * (ATTNCH / 2) * HW];
__device__ uint32_t g_attl [(size_t)NB * (ATTNCH / 2) * HW];
__device__ uint32_t g_wqh  [QKVCH * (CIN / 2)];
__device__ uint32_t g_wql  [QKVCH * (CIN / 2)];
__device__ uint32_t g_wph  [CIN * (ATTNCH / 2)];
__device__ uint32_t g_wpl  [CIN * (ATTNCH / 2)];

// ===========================================================================
// Helpers
// ===========================================================================
__device__ __forceinline__ void split_bf16(float x, uint16_t& h, uint16_t& l) {
    __nv_bfloat16 hb = __float2bfloat16_rn(x);
    float r = x - __bfloat162float(hb);
    __nv_bfloat16 lb = __float2bfloat16_rn(r);
    h = __nv_bfloat16_raw(hb).x;
    l = __nv_bfloat16_raw(lb).x;
}
__device__ __forceinline__ uint32_t pack2(uint16_t lo16, uint16_t hi16) {
    return (uint32_t)lo16 | ((uint32_t)hi16 << 16);
}
__device__ __forceinline__ void mma_bf16(float d[4], const uint32_t a[4],
                                         uint32_t b0, uint32_t b1) {
    asm volatile(
        "mma.sync.aligned.m16n8k16.row.col.f32.bf16.bf16.f32 "
        "{%0,%1,%2,%3}, {%4,%5,%6,%7}, {%8,%9}, {%0,%1,%2,%3};\n"
        : "+f"(d[0]), "+f"(d[1]), "+f"(d[2]), "+f"(d[3])
        : "r"(a[0]), "r"(a[1]), "r"(a[2]), "r"(a[3]), "r"(b0), "r"(b1));
}
__device__ __forceinline__ void cpasync16(uint32_t* smem_dst, const uint32_t* gsrc) {
    uint32_t s = (uint32_t)__cvta_generic_to_shared(smem_dst);
    asm volatile("cp.async.ca.shared.global [%0], [%1], 16;" :: "r"(s), "l"(gsrc));
}

// ===========================================================================
// Pre-split kernels
// ===========================================================================
// Weights [O][K] row-major -> packed [O][K/2]
__global__ void presplit_w_kernel(const float* __restrict__ w,
                                  uint32_t* __restrict__ wh,
                                  uint32_t* __restrict__ wl, int nwords) {
    int i = blockIdx.x * blockDim.x + threadIdx.x;
    if (i >= nwords) return;
    float2 v = ((const float2*)w)[i];
    uint16_t h0, l0, h1, l1;
    split_bf16(v.x, h0, l0); split_bf16(v.y, h1, l1);
    wh[i] = pack2(h0, h1);
    wl[i] = pack2(l0, l1);
}
// Acts [B][C][HW] -> packed [B][C/2][HW]; 4 pixels per thread
__global__ void presplit_x_kernel(const float* __restrict__ x,
                                  uint32_t* __restrict__ xh,
                                  uint32_t* __restrict__ xl) {
    int i = blockIdx.x * blockDim.x + threadIdx.x;   // quad index
    int p4  = i & (HW / 4 - 1);
    int cpb = i >> 10;                               // b*(CIN/2)+cp
    int cp  = cpb & (CIN / 2 - 1);
    int b   = cpb >> 8;
    const float* s = x + ((size_t)(b * CIN + 2 * cp)) * HW + p4 * 4;
    float4 a = *(const float4*)s;
    float4 c = *(const float4*)(s + HW);
    uint16_t ha[4], la[4], hc[4], lc[4];
    split_bf16(a.x, ha[0], la[0]); split_bf16(a.y, ha[1], la[1]);
    split_bf16(a.z, ha[2], la[2]); split_bf16(a.w, ha[3], la[3]);
    split_bf16(c.x, hc[0], lc[0]); split_bf16(c.y, hc[1], lc[1]);
    split_bf16(c.z, hc[2], lc[2]); split_bf16(c.w, hc[3], lc[3]);
    uint4 hv = make_uint4(pack2(ha[0], hc[0]), pack2(ha[1], hc[1]),
                          pack2(ha[2], hc[2]), pack2(ha[3], hc[3]));
    uint4 lv = make_uint4(pack2(la[0], lc[0]), pack2(la[1], lc[1]),
                          pack2(la[2], lc[2]), pack2(la[3], lc[3]));
    size_t o = (size_t)cpb * HW + p4 * 4;
    *(uint4*)(xh + o) = hv;
    *(uint4*)(xl + o) = lv;
}

// ===========================================================================
// tensor GEMM with cp.async double buffering (no in-loop conversion)
// C[b][o][p] = sum_c W[o][c]*Act[b][c][p];  tile 128o x 128p x k32
// ===========================================================================
#define A_STRIDE 20
#define B_STRIDE 136
#define ST_AH 0
#define ST_AL 2560
#define ST_BH 5120
#define ST_BL 7296
#define ST_WORDS 9472
#define SMEM_BYTES (2 * ST_WORDS * 4)

__device__ __forceinline__ void stage_tile(uint32_t* sbase, int t, int KW,
                                           const uint32_t* ahr, const uint32_t* alr,
                                           const uint32_t* bhr, const uint32_t* blr) {
#pragma unroll
    for (int r = 0; r < 2; r++) {
        int id = t + r * 256, o = id >> 2, cc = (id & 3) * 4;
        cpasync16(sbase + ST_AH + o * A_STRIDE + cc, ahr + (size_t)o * KW + cc);
        cpasync16(sbase + ST_AL + o * A_STRIDE + cc, alr + (size_t)o * KW + cc);
    }
#pragma unroll
    for (int r = 0; r < 2; r++) {
        int id = t + r * 256, kp = id >> 5, cc = (id & 31) * 4;
        cpasync16(sbase + ST_BH + kp * B_STRIDE + cc, bhr + (size_t)kp * HW + cc);
        cpasync16(sbase + ST_BL + kp * B_STRIDE + cc, blr + (size_t)kp * HW + cc);
    }
    asm volatile("cp.async.commit_group;" ::: "memory");
}

template <bool BN>
__global__ __launch_bounds__(256, 2)
void mma_gemm_kernel(const uint32_t* __restrict__ Bh_g,   // acts packed [B][KW][HW]
                     const uint32_t* __restrict__ Bl_g,
                     const uint32_t* __restrict__ Ah_g,   // weights packed [O][KW]
                     const uint32_t* __restrict__ Al_g,
                     float* __restrict__ C, int K, int Ochan,
                     const float* __restrict__ bn_gamma,
                     const float* __restrict__ bn_beta,
                     const float* __restrict__ bn_mean,
                     const float* __restrict__ bn_var)
{
    extern __shared__ uint32_t smw[];
    const int KW = K >> 1;
    const int t = threadIdx.x, lane = t & 31, wid = t >> 5;
    const int wm = wid & 3, wn = wid >> 2;
    const int bx = blockIdx.x;
    const int b  = bx >> 5;
    const int p0 = (bx & 31) * 128;
    const int o0 = blockIdx.y * 128;

    const uint32_t* Bhb = Bh_g + (size_t)b * KW * HW + p0;
    const uint32_t* Blb = Bl_g + (size_t)b * KW * HW + p0;
    const uint32_t* Ahb = Ah_g + (size_t)o0 * KW;
    const uint32_t* Alb = Al_g + (size_t)o0 * KW;

    float acc[2][8][4];
#pragma unroll
    for (int i = 0; i < 2; i++)
#pragma unroll
        for (int j = 0; j < 8; j++)
#pragma unroll
            for (int e = 0; e < 4; e++) acc[i][j][e] = 0.f;

    const int NT = K / 32;
    stage_tile(smw, t, KW, Ahb, Alb, Bhb, Blb);

    for (int kt = 0; kt < NT; kt++) {
        if (kt + 1 < NT) {
            int kw0 = (kt + 1) * 16;
            stage_tile(smw + ((kt + 1) & 1) * ST_WORDS, t, KW,
                       Ahb + kw0, Alb + kw0,
                       Bhb + (size_t)kw0 * HW, Blb + (size_t)kw0 * HW);
            asm volatile("cp.async.wait_group 1;" ::: "memory");
        } else {
            asm volatile("cp.async.wait_group 0;" ::: "memory");
        }
        __syncthreads();

        const uint32_t* sAh = smw + (kt & 1) * ST_WORDS + ST_AH;
        const uint32_t* sAl = smw + (kt & 1) * ST_WORDS + ST_AL;
        const uint32_t* sBh = smw + (kt & 1) * ST_WORDS + ST_BH;
        const uint32_t* sBl = smw + (kt & 1) * ST_WORDS + ST_BL;

#pragma unroll
        for (int s = 0; s < 2; s++) {
            uint32_t ah[2][4], al[2][4];
            int baseA = (wm * 32 + (lane >> 2)) * A_STRIDE + s * 8 + (lane & 3);
#pragma unroll
            for (int i = 0; i < 2; i++) {
                int ba = baseA + i * 16 * A_STRIDE;
                ah[i][0] = sAh[ba];
                ah[i][1] = sAh[ba + 8 * A_STRIDE];
                ah[i][2] = sAh[ba + 4];
                ah[i][3] = sAh[ba + 8 * A_STRIDE + 4];
                al[i][0] = sAl[ba];
                al[i][1] = sAl[ba + 8 * A_STRIDE];
                al[i][2] = sAl[ba + 4];
                al[i][3] = sAl[ba + 8 * A_STRIDE + 4];
            }
            int baseB = (s * 8 + (lane & 3)) * B_STRIDE + wn * 64 + (lane >> 2);
#pragma unroll
            for (int j = 0; j < 8; j++) {
                uint32_t bh0 = sBh[baseB + 8 * j];
                uint32_t bh1 = sBh[baseB + 4 * B_STRIDE + 8 * j];
                uint32_t bl0 = sBl[baseB + 8 * j];
                uint32_t bl1 = sBl[baseB + 4 * B_STRIDE + 8 * j];
#pragma unroll
                for (int i = 0; i < 2; i++) {
                    mma_bf16(acc[i][j], ah[i], bh0, bh1);
                    mma_bf16(acc[i][j], ah[i], bl0, bl1);
                    mma_bf16(acc[i][j], al[i], bh0, bh1);
                }
            }
        }
        __syncthreads();
    }

    // ---- epilogue (optional fused BN affine) ----
    const int orow = o0 + wm * 32 + (lane >> 2);
    float scl[4], bia[4];
#pragma unroll
    for (int r = 0; r < 4; r++) {
        if (BN) {
            int o = orow + 8 * r;
            float inv = bn_gamma[o] * rsqrtf(bn_var[o] + BNEPS);
            scl[r] = inv;
            bia[r] = bn_beta[o] - bn_mean[o] * inv;
        } else { scl[r] = 1.f; bia[r] = 0.f; }
    }
    float* Cb = C + (size_t)b * Ochan * HW;
    const int pbase = p0 + wn * 64 + (lane & 3) * 2;
#pragma unroll
    for (int i = 0; i < 2; i++) {
        int oA = orow + 16 * i;
        int r0 = 2 * i;
#pragma unroll
        for (int j = 0; j < 8; j++) {
            int p = pbase + 8 * j;
            float2 v0, v1;
            v0.x = acc[i][j][0] * scl[r0] + bia[r0];
            v0.y = acc[i][j][1] * scl[r0] + bia[r0];
            v1.x = acc[i][j][2] * scl[r0 + 1] + bia[r0 + 1];
            v1.y = acc[i][j][3] * scl[r0 + 1] + bia[r0 + 1];
            *(float2*)&Cb[(size_t)oA * HW + p]       = v0;
            *(float2*)&Cb[(size_t)(oA + 8) * HW + p] = v1;
        }
    }
}

// ---------------------------------------------------------------------------
// Fused depthwise 5x5 conv (pad 2) + grouped 8x8 pointwise mix.
// ---------------------------------------------------------------------------
__global__ __launch_bounds__(256)
void dwpw_kernel(const float* __restrict__ w_dw,
                 const float* __restrict__ w_pw)
{
    const int TR = 8;
    const int b  = blockIdx.z;
    const int g  = blockIdx.y;
    const int r0 = blockIdx.x * TR;
    const int t  = threadIdx.x;

    __shared__ float sin_[8][TR + 4][68];
    __shared__ float swdw[8][25];
    __shared__ float swpw[64];

    const float* src = g_qkv + ((size_t)b * QKVCH + g * 8) * HW;
    float*       dst = g_agg + ((size_t)b * QKVCH + g * 8) * HW;

    if (t < 200) swdw[t / 25][t % 25] = w_dw[(size_t)(g * 8 + t / 25) * 25 + (t % 25)];
    if (t < 64)  swpw[t] = w_pw[(size_t)g * 64 + t];

    for (int idx = t; idx < 8 * (TR + 4) * 68; idx += 256) {
        int i   = idx / ((TR + 4) * 68);
        int rem = idx % ((TR + 4) * 68);
        int rr  = rem / 68, cc = rem % 68;
        int gr  = r0 + rr - 2, gc = cc - 2;
        float v = 0.f;
        if (gr >= 0 && gr < HH && gc >= 0 && gc < WW)
            v = src[(size_t)i * HW + gr * WW + gc];
        sin_[i][rr][cc] = v;
    }
    __syncthreads();

    for (int px = t; px < TR * WW; px += 256) {
        int rr = px >> 6, cc = px & 63;
        float dwv[8];
#pragma unroll
        for (int i = 0; i < 8; i++) {
            float s = 0.f;
#pragma unroll
            for (int dy = 0; dy < 5; dy++)
#pragma unroll
                for (int dx = 0; dx < 5; dx++)
                    s = fmaf(sin_[i][rr + dy][cc + dx], swdw[i][dy * 5 + dx], s);
            dwv[i] = s;
        }
        int pout = (r0 + rr) * WW + cc;
#pragma unroll
        for (int o = 0; o < 8; o++) {
            float s = 0.f;
#pragma unroll
            for (int i = 0; i < 8; i++) s = fmaf(dwv[i], swpw[o * 8 + i], s);
            dst[(size_t)o * HW + pout] = s;
        }
    }
}

// ---------------------------------------------------------------------------
// Linear attention per (batch, head); writes PRE-SPLIT packed output.
// ---------------------------------------------------------------------------
__global__ __launch_bounds__(256)
void attn_kernel()
{
    const int b = blockIdx.y;
    const int h = blockIdx.x;
    const int t = threadIdx.x;

    const float* base = (h < 64)
        ? g_qkv + ((size_t)b * QKVCH + h * 24) * HW
        : g_agg + ((size_t)b * QKVCH + (h - 64) * 24) * HW;

    float kv[72];
#pragma unroll
    for (int i = 0; i < 72; i++) kv[i] = 0.f;

    for (int p = t; p < HW; p += 256) {
        float kd[8], ve[8];
#pragma unroll
        for (int d = 0; d < 8; d++) kd[d] = fmaxf(base[(size_t)(8 + d) * HW + p], 0.f);
#pragma unroll
        for (int e = 0; e < 8; e++) ve[e] = base[(size_t)(16 + e) * HW + p];
#pragma unroll
        for (int d = 0; d < 8; d++) {
#pragma unroll
            for (int e = 0; e < 8; e++) kv[d * 9 + e] = fmaf(kd[d], ve[e], kv[d * 9 + e]);
            kv[d * 9 + 8] += kd[d];
        }
    }

    __shared__ float red[8][72];
    __shared__ float kvf[72];
#pragma unroll
    for (int i = 0; i < 72; i++) {
        float v = kv[i];
        v += __shfl_xor_sync(0xffffffffu, v, 16);
        v += __shfl_xor_sync(0xffffffffu, v, 8);
        v += __shfl_xor_sync(0xffffffffu, v, 4);
        v += __shfl_xor_sync(0xffffffffu, v, 2);
        v += __shfl_xor_sync(0xffffffffu, v, 1);
        kv[i] = v;
    }
    const int lane = t & 31, wid = t >> 5;
    if (lane == 0) {
#pragma unroll
        for (int i = 0; i < 72; i++) red[wid][i] = kv[i];
    }
    __syncthreads();
    if (t < 72) {
        float s = 0.f;
#pragma unroll
        for (int w = 0; w < 8; w++) s += red[w][t];
        kvf[t] = s;
    }
    __syncthreads();

    uint32_t* dsth = g_atth + ((size_t)b * (ATTNCH / 2) + h * 4) * HW;
    uint32_t* dstl = g_attl + ((size_t)b * (ATTNCH / 2) + h * 4) * HW;
    for (int p = t; p < HW; p += 256) {
        float qd[8];
#pragma unroll
        for (int d = 0; d < 8; d++) qd[d] = fmaxf(base[(size_t)d * HW + p], 0.f);
        float num[9];
#pragma unroll
        for (int e = 0; e < 9; e++) {
            float s = 0.f;
#pragma unroll
            for (int d = 0; d < 8; d++) s = fmaf(qd[d], kvf[d * 9 + e], s);
            num[e] = s;
        }
        float inv = 1.f / (num[8] + EPSV);
#pragma unroll
        for (int j = 0; j < 4; j++) {
            uint16_t h0, l0, h1, l1;
            split_bf16(num[2 * j] * inv, h0, l0);
            split_bf16(num[2 * j + 1] * inv, h1, l1);
            dsth[(size_t)j * HW + p] = pack2(h0, h1);
            dstl[(size_t)j * HW + p] = pack2(l0, l1);
        }
    }
}

// ---------------------------------------------------------------------------
extern "C" void kernel_launch(void* const* d_in, const int* in_sizes, int n_in,
                              void* d_out, int out_size)
{
    const float* x       = (const float*)d_in[0];
    const float* w_qkv   = (const float*)d_in[1];
    const float* w_dw    = (const float*)d_in[2];
    const float* w_pw    = (const float*)d_in[3];
    const float* w_proj  = (const float*)d_in[4];
    const float* bn_g    = (const float*)d_in[5];
    const float* bn_b    = (const float*)d_in[6];
    const float* bn_m    = (const float*)d_in[7];
    const float* bn_v    = (const float*)d_in[8];
    float* out = (float*)d_out;

    float *qkv_p;
    uint32_t *xh_p, *xl_p, *ath_p, *atl_p, *wqh_p, *wql_p, *wph_p, *wpl_p;
    cudaGetSymbolAddress((void**)&qkv_p, g_qkv);
    cudaGetSymbolAddress((void**)&xh_p,  g_xh);
    cudaGetSymbolAddress((void**)&xl_p,  g_xl);
    cudaGetSymbolAddress((void**)&ath_p, g_atth);
    cudaGetSymbolAddress((void**)&atl_p, g_attl);
    cudaGetSymbolAddress((void**)&wqh_p, g_wqh);
    cudaGetSymbolAddress((void**)&wql_p, g_wql);
    cudaGetSymbolAddress((void**)&wph_p, g_wph);
    cudaGetSymbolAddress((void**)&wpl_p, g_wpl);

    cudaFuncSetAttribute(mma_gemm_kernel<false>,
                         cudaFuncAttributeMaxDynamicSharedMemorySize, SMEM_BYTES);
    cudaFuncSetAttribute(mma_gemm_kernel<true>,
                         cudaFuncAttributeMaxDynamicSharedMemorySize, SMEM_BYTES);

    // 0) pre-split weights + x
    presplit_w_kernel<<<(QKVCH * (CIN / 2) + 255) / 256, 256>>>(
        w_qkv, wqh_p, wql_p, QKVCH * (CIN / 2));
    presplit_w_kernel<<<(CIN * (ATTNCH / 2) + 255) / 256, 256>>>(
        w_proj, wph_p, wpl_p, CIN * (ATTNCH / 2));
    presplit_x_kernel<<<(NB * (CIN / 2) * HW / 4) / 256, 256>>>(x, xh_p, xl_p);

    // 1) qkv = x @ w_qkv   (K=512, O=1536)
    mma_gemm_kernel<false><<<dim3(128, QKVCH / 128), 256, SMEM_BYTES>>>(
        xh_p, xl_p, wqh_p, wql_p, qkv_p, CIN, QKVCH,
        nullptr, nullptr, nullptr, nullptr);

    // 2) depthwise 5x5 + grouped pointwise 8x8
    dwpw_kernel<<<dim3(HH / 8, NGROUP, NB), 256>>>(w_dw, w_pw);

    // 3) linear attention (128 heads) -> pre-split packed output
    attn_kernel<<<dim3(NHEAD, NB), 256>>>();

    // 4) proj GEMM (K=1024, O=512) + BN affine
    mma_gemm_kernel<true><<<dim3(128, CIN / 128), 256, SMEM_BYTES>>>(
        ath_p, atl_p, wph_p, wpl_p, out, ATTNCH, CIN,
        bn_g, bn_b, bn_m, bn_v);
}

// round 11
// speedup vs baseline: 1.8839x; 1.0434x over previous
#include <cuda_runtime.h>
#include <cuda_bf16.h>
#include <math.h>
#include <stdint.h>

// Problem constants
#define NB      4
#define CIN     512
#define HH      64
#define WW      64
#define HW      4096
#define QKVCH   1536
#define NGROUP  192
#define NHEAD   128
#define ATTNCH  1024
#define EPSV    1e-5f
#define BNEPS   1e-5f

#define KWX  (CIN / 2)      // 256 words per pixel row (x)
#define KWA  (ATTNCH / 2)   // 512 words per pixel row (attn out)

// Scratch: fp32 intermediates
__device__ float g_qkv [(size_t)NB * QKVCH * HW];
__device__ float g_agg [(size_t)NB * QKVCH * HW];
// Packed k-pair bf16, PIXEL-MAJOR: word[p][kw] = bf16(ch 2kw) | bf16(ch 2kw+1)<<16
__device__ uint32_t g_xh   [(size_t)NB * HW * KWX];
__device__ uint32_t g_xl   [(size_t)NB * HW * KWX];
__device__ uint32_t g_atth [(size_t)NB * HW * KWA];
__device__ uint32_t g_attl [(size_t)NB * HW * KWA];
// Weights packed [o][kw] (k-major rows)
__device__ uint32_t g_wqh  [QKVCH * KWX];
__device__ uint32_t g_wql  [QKVCH * KWX];
__device__ uint32_t g_wph  [CIN * KWA];
__device__ uint32_t g_wpl  [CIN * KWA];

// ===========================================================================
// Helpers
// ===========================================================================
__device__ __forceinline__ void split_bf16(float x, uint16_t& h, uint16_t& l) {
    __nv_bfloat16 hb = __float2bfloat16_rn(x);
    float r = x - __bfloat162float(hb);
    __nv_bfloat16 lb = __float2bfloat16_rn(r);
    h = __nv_bfloat16_raw(hb).x;
    l = __nv_bfloat16_raw(lb).x;
}
__device__ __forceinline__ uint32_t pack2(uint16_t lo16, uint16_t hi16) {
    return (uint32_t)lo16 | ((uint32_t)hi16 << 16);
}
__device__ __forceinline__ void mma_bf16(float d[4], const uint32_t a[4],
                                         uint32_t b0, uint32_t b1) {
    asm volatile(
        "mma.sync.aligned.m16n8k16.row.col.f32.bf16.bf16.f32 "
        "{%0,%1,%2,%3}, {%4,%5,%6,%7}, {%8,%9}, {%0,%1,%2,%3};\n"
        : "+f"(d[0]), "+f"(d[1]), "+f"(d[2]), "+f"(d[3])
        : "r"(a[0]), "r"(a[1]), "r"(a[2]), "r"(a[3]), "r"(b0), "r"(b1));
}
__device__ __forceinline__ void cpasync16(uint32_t* smem_dst, const uint32_t* gsrc) {
    uint32_t s = (uint32_t)__cvta_generic_to_shared(smem_dst);
    asm volatile("cp.async.ca.shared.global [%0], [%1], 16;" :: "r"(s), "l"(gsrc));
}
#define LDSM_X4(r, addr)                                                      \
    asm volatile("ldmatrix.sync.aligned.m8n8.x4.shared.b16 {%0,%1,%2,%3}, [%4];" \
        : "=r"((r)[0]), "=r"((r)[1]), "=r"((r)[2]), "=r"((r)[3]) : "r"(addr))

// ===========================================================================
// Pre-split kernels
// ===========================================================================
// Weights [O][K] row-major -> 2-term packed [O][K/2]
__global__ void presplit_w_kernel(const float* __restrict__ w,
                                  uint32_t* __restrict__ wh,
                                  uint32_t* __restrict__ wl, int nwords) {
    int i = blockIdx.x * blockDim.x + threadIdx.x;
    if (i >= nwords) return;
    float2 v = ((const float2*)w)[i];
    uint16_t h0, l0, h1, l1;
    split_bf16(v.x, h0, l0); split_bf16(v.y, h1, l1);
    wh[i] = pack2(h0, h1);
    wl[i] = pack2(l0, l1);
}
// Acts [B][C][HW] -> pixel-major packed [B][HW][KWX] via smem transpose.
// Tile: 32 pixels x 64 channel-pairs per block.
__global__ __launch_bounds__(256)
void presplit_x_kernel(const float* __restrict__ x,
                       uint32_t* __restrict__ xh,
                       uint32_t* __restrict__ xl) {
    __shared__ uint32_t th[64][33];
    __shared__ uint32_t tl[64][33];
    const int t   = threadIdx.x;
    const int b   = blockIdx.z;
    const int cp0 = blockIdx.y * 64;
    const int p0  = blockIdx.x * 32;

#pragma unroll
    for (int it = 0; it < 8; it++) {
        int cp = it * 8 + (t >> 5);
        int p  = t & 31;
        const float* s = x + ((size_t)(b * CIN + 2 * (cp0 + cp))) * HW + p0 + p;
        float a = s[0];
        float c = s[HW];
        uint16_t ha, la, hc, lc;
        split_bf16(a, ha, la); split_bf16(c, hc, lc);
        th[cp][p] = pack2(ha, hc);
        tl[cp][p] = pack2(la, lc);
    }
    __syncthreads();

#pragma unroll
    for (int it = 0; it < 2; it++) {
        int idx = t + it * 256;            // 0..511
        int p   = idx >> 4;
        int c4  = (idx & 15) * 4;
        uint4 hv = make_uint4(th[c4][p], th[c4 + 1][p], th[c4 + 2][p], th[c4 + 3][p]);
        uint4 lv = make_uint4(tl[c4][p], tl[c4 + 1][p], tl[c4 + 2][p], tl[c4 + 3][p]);
        size_t o = ((size_t)b * HW + p0 + p) * KWX + cp0 + c4;
        *(uint4*)(xh + o) = hv;
        *(uint4*)(xl + o) = lv;
    }
}

// ===========================================================================
// tensor GEMM, 2-stage cp.async pipeline, ldmatrix fragments.
// C[b][o][p] = sum_c W[o][c]*Act[b][c][p];  tile 128o x 128p x k32
// Weights [o][kw] 2-term, acts [p][kw] 2-term; 3 MMAs (drop lo*lo).
// ===========================================================================
#define STRIDE20 20
#define ST_AH 0
#define ST_AL 2560
#define ST_BH 5120
#define ST_BL 7680
#define ST_WORDS 10240
#define SMEM_BYTES (2 * ST_WORDS * 4)

__device__ __forceinline__ void stage_tile(uint32_t* sbase, int t, int KW,
                                           const uint32_t* ahr, const uint32_t* alr,
                                           const uint32_t* bhr, const uint32_t* blr) {
#pragma unroll
    for (int r = 0; r < 2; r++) {
        int id = t + r * 256, o = id >> 2, c4 = (id & 3) * 4;
        cpasync16(sbase + ST_AH + o * STRIDE20 + c4, ahr + (size_t)o * KW + c4);
        cpasync16(sbase + ST_AL + o * STRIDE20 + c4, alr + (size_t)o * KW + c4);
    }
#pragma unroll
    for (int r = 0; r < 2; r++) {
        int id = t + r * 256, n = id >> 2, c4 = (id & 3) * 4;
        cpasync16(sbase + ST_BH + n * STRIDE20 + c4, bhr + (size_t)n * KW + c4);
        cpasync16(sbase + ST_BL + n * STRIDE20 + c4, blr + (size_t)n * KW + c4);
    }
    asm volatile("cp.async.commit_group;" ::: "memory");
}

template <bool BN>
__global__ __launch_bounds__(256, 2)
void mma_gemm_kernel(const uint32_t* __restrict__ Bh_g,   // acts [B][HW][KW]
                     const uint32_t* __restrict__ Bl_g,
                     const uint32_t* __restrict__ Ah_g,   // weights [O][KW]
                     const uint32_t* __restrict__ Al_g,
                     float* __restrict__ C, int K, int Ochan,
                     const float* __restrict__ bn_gamma,
                     const float* __restrict__ bn_beta,
                     const float* __restrict__ bn_mean,
                     const float* __restrict__ bn_var)
{
    extern __shared__ uint32_t smw[];
    const int KW = K >> 1;
    const int t = threadIdx.x, lane = t & 31, wid = t >> 5;
    const int wm = wid & 3, wn = wid >> 2;
    const int bx = blockIdx.x;
    const int b  = bx >> 5;
    const int p0 = (bx & 31) * 128;
    const int o0 = blockIdx.y * 128;

    const uint32_t* Bhb = Bh_g + ((size_t)b * HW + p0) * KW;
    const uint32_t* Blb = Bl_g + ((size_t)b * HW + p0) * KW;
    const uint32_t* Ahb = Ah_g + (size_t)o0 * KW;
    const uint32_t* Alb = Al_g + (size_t)o0 * KW;

    // Per-lane ldmatrix byte offsets (within a stage buffer)
    uint32_t aoff[2];
#pragma unroll
    for (int i = 0; i < 2; i++)
        aoff[i] = ((wm * 32 + i * 16 + (lane & 15)) * STRIDE20 +
                   ((lane >> 4) & 1) * 4) * 4;
    uint32_t boff[4];
#pragma unroll
    for (int jj = 0; jj < 4; jj++)
        boff[jj] = ((wn * 64 + jj * 16 + (lane & 7) + ((lane >> 4) & 1) * 8) * STRIDE20 +
                    ((lane >> 3) & 1) * 4) * 4;

    const uint32_t smem32 = (uint32_t)__cvta_generic_to_shared(smw);

    float acc[2][8][4];
#pragma unroll
    for (int i = 0; i < 2; i++)
#pragma unroll
        for (int j = 0; j < 8; j++)
#pragma unroll
            for (int e = 0; e < 4; e++) acc[i][j][e] = 0.f;

    const int NT = K / 32;
    stage_tile(smw, t, KW, Ahb, Alb, Bhb, Blb);

    for (int kt = 0; kt < NT; kt++) {
        if (kt + 1 < NT) {
            int kw0 = (kt + 1) * 16;
            stage_tile(smw + ((kt + 1) & 1) * ST_WORDS, t, KW,
                       Ahb + kw0, Alb + kw0, Bhb + kw0, Blb + kw0);
            asm volatile("cp.async.wait_group 1;" ::: "memory");
        } else {
            asm volatile("cp.async.wait_group 0;" ::: "memory");
        }
        __syncthreads();

        const uint32_t sb = smem32 + ((kt & 1) ? ST_WORDS * 4 : 0);

#pragma unroll
        for (int s = 0; s < 2; s++) {
            const uint32_t sd = s * 32;   // +8 kp words = 32 bytes
            uint32_t ah[2][4], al[2][4], bb[4][4];
#pragma unroll
            for (int i = 0; i < 2; i++) {
                LDSM_X4(ah[i], sb + ST_AH * 4 + aoff[i] + sd);
                LDSM_X4(al[i], sb + ST_AL * 4 + aoff[i] + sd);
            }
            // B hi
#pragma unroll
            for (int jj = 0; jj < 4; jj++)
                LDSM_X4(bb[jj], sb + ST_BH * 4 + boff[jj] + sd);
#pragma unroll
            for (int jj = 0; jj < 4; jj++)
#pragma unroll
                for (int h = 0; h < 2; h++) {
                    int j = 2 * jj + h;
                    uint32_t b0 = bb[jj][2 * h], b1 = bb[jj][2 * h + 1];
#pragma unroll
                    for (int i = 0; i < 2; i++) {
                        mma_bf16(acc[i][j], ah[i], b0, b1);
                        mma_bf16(acc[i][j], al[i], b0, b1);
                    }
                }
            // B lo (reuse regs)
#pragma unroll
            for (int jj = 0; jj < 4; jj++)
                LDSM_X4(bb[jj], sb + ST_BL * 4 + boff[jj] + sd);
#pragma unroll
            for (int jj = 0; jj < 4; jj++)
#pragma unroll
                for (int h = 0; h < 2; h++) {
                    int j = 2 * jj + h;
                    uint32_t b0 = bb[jj][2 * h], b1 = bb[jj][2 * h + 1];
#pragma unroll
                    for (int i = 0; i < 2; i++)
                        mma_bf16(acc[i][j], ah[i], b0, b1);
                }
        }
        __syncthreads();
    }

    // ---- epilogue (optional fused BN affine) ----
    const int orow = o0 + wm * 32 + (lane >> 2);
    float scl[4], bia[4];
#pragma unroll
    for (int r = 0; r < 4; r++) {
        if (BN) {
            int o = orow + 8 * r;
            float inv = bn_gamma[o] * rsqrtf(bn_var[o] + BNEPS);
            scl[r] = inv;
            bia[r] = bn_beta[o] - bn_mean[o] * inv;
        } else { scl[r] = 1.f; bia[r] = 0.f; }
    }
    float* Cb = C + (size_t)b * Ochan * HW;
    const int pbase = p0 + wn * 64 + (lane & 3) * 2;
#pragma unroll
    for (int i = 0; i < 2; i++) {
        int oA = orow + 16 * i;
        int r0 = 2 * i;
#pragma unroll
        for (int j = 0; j < 8; j++) {
            int p = pbase + 8 * j;
            float2 v0, v1;
            v0.x = acc[i][j][0] * scl[r0] + bia[r0];
            v0.y = acc[i][j][1] * scl[r0] + bia[r0];
            v1.x = acc[i][j][2] * scl[r0 + 1] + bia[r0 + 1];
            v1.y = acc[i][j][3] * scl[r0 + 1] + bia[r0 + 1];
            *(float2*)&Cb[(size_t)oA * HW + p]       = v0;
            *(float2*)&Cb[(size_t)(oA + 8) * HW + p] = v1;
        }
    }
}

// ---------------------------------------------------------------------------
// Fused depthwise 5x5 conv (pad 2) + grouped 8x8 pointwise mix.
// ---------------------------------------------------------------------------
__global__ __launch_bounds__(256)
void dwpw_kernel(const float* __restrict__ w_dw,
                 const float* __restrict__ w_pw)
{
    const int TR = 8;
    const int b  = blockIdx.z;
    const int g  = blockIdx.y;
    const int r0 = blockIdx.x * TR;
    const int t  = threadIdx.x;

    __shared__ float sin_[8][TR + 4][68];
    __shared__ float swdw[8][25];
    __shared__ float swpw[64];

    const float* src = g_qkv + ((size_t)b * QKVCH + g * 8) * HW;
    float*       dst = g_agg + ((size_t)b * QKVCH + g * 8) * HW;

    if (t < 200) swdw[t / 25][t % 25] = w_dw[(size_t)(g * 8 + t / 25) * 25 + (t % 25)];
    if (t < 64)  swpw[t] = w_pw[(size_t)g * 64 + t];

    for (int idx = t; idx < 8 * (TR + 4) * 68; idx += 256) {
        int i   = idx / ((TR + 4) * 68);
        int rem = idx % ((TR + 4) * 68);
        int rr  = rem / 68, cc = rem % 68;
        int gr  = r0 + rr - 2, gc = cc - 2;
        float v = 0.f;
        if (gr >= 0 && gr < HH && gc >= 0 && gc < WW)
            v = src[(size_t)i * HW + gr * WW + gc];
        sin_[i][rr][cc] = v;
    }
    __syncthreads();

    for (int px = t; px < TR * WW; px += 256) {
        int rr = px >> 6, cc = px & 63;
        float dwv[8];
#pragma unroll
        for (int i = 0; i < 8; i++) {
            float s = 0.f;
#pragma unroll
            for (int dy = 0; dy < 5; dy++)
#pragma unroll
                for (int dx = 0; dx < 5; dx++)
                    s = fmaf(sin_[i][rr + dy][cc + dx], swdw[i][dy * 5 + dx], s);
            dwv[i] = s;
        }
        int pout = (r0 + rr) * WW + cc;
#pragma unroll
        for (int o = 0; o < 8; o++) {
            float s = 0.f;
#pragma unroll
            for (int i = 0; i < 8; i++) s = fmaf(dwv[i], swpw[o * 8 + i], s);
            dst[(size_t)o * HW + pout] = s;
        }
    }
}

// ---------------------------------------------------------------------------
// Linear attention per (batch, head); writes packed bf16 hi/lo, pixel-major.
// ---------------------------------------------------------------------------
__global__ __launch_bounds__(256)
void attn_kernel()
{
    const int b = blockIdx.y;
    const int h = blockIdx.x;
    const int t = threadIdx.x;

    const float* base = (h < 64)
        ? g_qkv + ((size_t)b * QKVCH + h * 24) * HW
        : g_agg + ((size_t)b * QKVCH + (h - 64) * 24) * HW;

    float kv[72];
#pragma unroll
    for (int i = 0; i < 72; i++) kv[i] = 0.f;

    for (int p = t; p < HW; p += 256) {
        float kd[8], ve[8];
#pragma unroll
        for (int d = 0; d < 8; d++) kd[d] = fmaxf(base[(size_t)(8 + d) * HW + p], 0.f);
#pragma unroll
        for (int e = 0; e < 8; e++) ve[e] = base[(size_t)(16 + e) * HW + p];
#pragma unroll
        for (int d = 0; d < 8; d++) {
#pragma unroll
            for (int e = 0; e < 8; e++) kv[d * 9 + e] = fmaf(kd[d], ve[e], kv[d * 9 + e]);
            kv[d * 9 + 8] += kd[d];
        }
    }

    __shared__ float red[8][72];
    __shared__ float kvf[72];
#pragma unroll
    for (int i = 0; i < 72; i++) {
        float v = kv[i];
        v += __shfl_xor_sync(0xffffffffu, v, 16);
        v += __shfl_xor_sync(0xffffffffu, v, 8);
        v += __shfl_xor_sync(0xffffffffu, v, 4);
        v += __shfl_xor_sync(0xffffffffu, v, 2);
        v += __shfl_xor_sync(0xffffffffu, v, 1);
        kv[i] = v;
    }
    const int lane = t & 31, wid = t >> 5;
    if (lane == 0) {
#pragma unroll
        for (int i = 0; i < 72; i++) red[wid][i] = kv[i];
    }
    __syncthreads();
    if (t < 72) {
        float s = 0.f;
#pragma unroll
        for (int w = 0; w < 8; w++) s += red[w][t];
        kvf[t] = s;
    }
    __syncthreads();

    uint32_t* dsth = g_atth + (size_t)b * HW * KWA + h * 4;
    uint32_t* dstl = g_attl + (size_t)b * HW * KWA + h * 4;
    for (int p = t; p < HW; p += 256) {
        float qd[8];
#pragma unroll
        for (int d = 0; d < 8; d++) qd[d] = fmaxf(base[(size_t)d * HW + p], 0.f);
        float num[9];
#pragma unroll
        for (int e = 0; e < 9; e++) {
            float s = 0.f;
#pragma unroll
            for (int d = 0; d < 8; d++) s = fmaf(qd[d], kvf[d * 9 + e], s);
            num[e] = s;
        }
        float inv = 1.f / (num[8] + EPSV);
        uint32_t hw4[4], lw4[4];
#pragma unroll
        for (int j = 0; j < 4; j++) {
            uint16_t h0, l0, h1, l1;
            split_bf16(num[2 * j] * inv, h0, l0);
            split_bf16(num[2 * j + 1] * inv, h1, l1);
            hw4[j] = pack2(h0, h1);
            lw4[j] = pack2(l0, l1);
        }
        *(uint4*)(dsth + (size_t)p * KWA) = make_uint4(hw4[0], hw4[1], hw4[2], hw4[3]);
        *(uint4*)(dstl + (size_t)p * KWA) = make_uint4(lw4[0], lw4[1], lw4[2], lw4[3]);
    }
}

// ---------------------------------------------------------------------------
extern "C" void kernel_launch(void* const* d_in, const int* in_sizes, int n_in,
                              void* d_out, int out_size)
{
    const float* x       = (const float*)d_in[0];
    const float* w_qkv   = (const float*)d_in[1];
    const float* w_dw    = (const float*)d_in[2];
    const float* w_pw    = (const float*)d_in[3];
    const float* w_proj  = (const float*)d_in[4];
    const float* bn_g    = (const float*)d_in[5];
    const float* bn_b    = (const float*)d_in[6];
    const float* bn_m    = (const float*)d_in[7];
    const float* bn_v    = (const float*)d_in[8];
    float* out = (float*)d_out;

    float *qkv_p;
    uint32_t *xh_p, *xl_p, *ath_p, *atl_p, *wqh_p, *wql_p, *wph_p, *wpl_p;
    cudaGetSymbolAddress((void**)&qkv_p, g_qkv);
    cudaGetSymbolAddress((void**)&xh_p,  g_xh);
    cudaGetSymbolAddress((void**)&xl_p,  g_xl);
    cudaGetSymbolAddress((void**)&ath_p, g_atth);
    cudaGetSymbolAddress((void**)&atl_p, g_attl);
    cudaGetSymbolAddress((void**)&wqh_p, g_wqh);
    cudaGetSymbolAddress((void**)&wql_p, g_wql);
    cudaGetSymbolAddress((void**)&wph_p, g_wph);
    cudaGetSymbolAddress((void**)&wpl_p, g_wpl);

    cudaFuncSetAttribute(mma_gemm_kernel<false>,
                         cudaFuncAttributeMaxDynamicSharedMemorySize, SMEM_BYTES);
    cudaFuncSetAttribute(mma_gemm_kernel<true>,
                         cudaFuncAttributeMaxDynamicSharedMemorySize, SMEM_BYTES);

    // 0) pre-split weights + x (x transposed to pixel-major)
    presplit_w_kernel<<<(QKVCH * KWX + 255) / 256, 256>>>(
        w_qkv, wqh_p, wql_p, QKVCH * KWX);
    presplit_w_kernel<<<(CIN * KWA + 255) / 256, 256>>>(
        w_proj, wph_p, wpl_p, CIN * KWA);
    presplit_x_kernel<<<dim3(HW / 32, CIN / 128, NB), 256>>>(x, xh_p, xl_p);

    // 1) qkv = x @ w_qkv   (K=512, O=1536)
    mma_gemm_kernel<false><<<dim3(128, QKVCH / 128), 256, SMEM_BYTES>>>(
        xh_p, xl_p, wqh_p, wql_p, qkv_p, CIN, QKVCH,
        nullptr, nullptr, nullptr, nullptr);

    // 2) depthwise 5x5 + grouped pointwise 8x8
    dwpw_kernel<<<dim3(HH / 8, NGROUP, NB), 256>>>(w_dw, w_pw);

    // 3) linear attention (128 heads) -> packed bf16 hi/lo, pixel-major
    attn_kernel<<<dim3(NHEAD, NB), 256>>>();

    // 4) proj GEMM (K=1024, O=512) + BN affine
    mma_gemm_kernel<true><<<dim3(128, CIN / 128), 256, SMEM_BYTES>>>(
        ath_p, atl_p, wph_p, wpl_p, out, ATTNCH, CIN,
        bn_g, bn_b, bn_m, bn_v);
}

// round 12
// speedup vs baseline: 2.7732x; 1.4720x over previous
#include <cuda_runtime.h>
#include <cuda_bf16.h>
#include <math.h>
#include <stdint.h>

// Problem constants
#define NB      4
#define CIN     512
#define HH      64
#define WW      64
#define HW      4096
#define QKVCH   1536
#define NGROUP  192
#define NHEAD   128
#define ATTNCH  1024
#define EPSV    1e-5f
#define BNEPS   1e-5f

#define KWX  (CIN / 2)      // 256 words per pixel row (x)
#define KWA  (ATTNCH / 2)   // 512 words per pixel row (attn out)

// Scratch: fp32 intermediates
__device__ float g_qkv [(size_t)NB * QKVCH * HW];
__device__ float g_agg [(size_t)NB * QKVCH * HW];
// Packed k-pair bf16, PIXEL-MAJOR: word[p][kw] = bf16(ch 2kw) | bf16(ch 2kw+1)<<16
__device__ uint32_t g_xh   [(size_t)NB * HW * KWX];
__device__ uint32_t g_xl   [(size_t)NB * HW * KWX];
__device__ uint32_t g_atth [(size_t)NB * HW * KWA];
__device__ uint32_t g_attl [(size_t)NB * HW * KWA];
// Weights packed [o][kw] (k-major rows)
__device__ uint32_t g_wqh  [QKVCH * KWX];
__device__ uint32_t g_wql  [QKVCH * KWX];
__device__ uint32_t g_wph  [CIN * KWA];
__device__ uint32_t g_wpl  [CIN * KWA];

// ===========================================================================
// Helpers
// ===========================================================================
__device__ __forceinline__ void split_bf16(float x, uint16_t& h, uint16_t& l) {
    __nv_bfloat16 hb = __float2bfloat16_rn(x);
    float r = x - __bfloat162float(hb);
    __nv_bfloat16 lb = __float2bfloat16_rn(r);
    h = __nv_bfloat16_raw(hb).x;
    l = __nv_bfloat16_raw(lb).x;
}
__device__ __forceinline__ uint32_t pack2(uint16_t lo16, uint16_t hi16) {
    return (uint32_t)lo16 | ((uint32_t)hi16 << 16);
}
__device__ __forceinline__ void mma_bf16(float d[4], const uint32_t a[4],
                                         uint32_t b0, uint32_t b1) {
    asm volatile(
        "mma.sync.aligned.m16n8k16.row.col.f32.bf16.bf16.f32 "
        "{%0,%1,%2,%3}, {%4,%5,%6,%7}, {%8,%9}, {%0,%1,%2,%3};\n"
        : "+f"(d[0]), "+f"(d[1]), "+f"(d[2]), "+f"(d[3])
        : "r"(a[0]), "r"(a[1]), "r"(a[2]), "r"(a[3]), "r"(b0), "r"(b1));
}
__device__ __forceinline__ void cpasync16(uint32_t* smem_dst, const uint32_t* gsrc) {
    uint32_t s = (uint32_t)__cvta_generic_to_shared(smem_dst);
    asm volatile("cp.async.ca.shared.global [%0], [%1], 16;" :: "r"(s), "l"(gsrc));
}
#define LDSM_X4(r, addr)                                                      \
    asm volatile("ldmatrix.sync.aligned.m8n8.x4.shared.b16 {%0,%1,%2,%3}, [%4];" \
        : "=r"((r)[0]), "=r"((r)[1]), "=r"((r)[2]), "=r"((r)[3]) : "r"(addr))

// ===========================================================================
// Pre-split kernels
// ===========================================================================
__global__ void presplit_w_kernel(const float* __restrict__ w,
                                  uint32_t* __restrict__ wh,
                                  uint32_t* __restrict__ wl, int nwords) {
    int i = blockIdx.x * blockDim.x + threadIdx.x;
    if (i >= nwords) return;
    float2 v = ((const float2*)w)[i];
    uint16_t h0, l0, h1, l1;
    split_bf16(v.x, h0, l0); split_bf16(v.y, h1, l1);
    wh[i] = pack2(h0, h1);
    wl[i] = pack2(l0, l1);
}
// Acts [B][C][HW] -> pixel-major packed [B][HW][KWX] via smem transpose.
__global__ __launch_bounds__(256)
void presplit_x_kernel(const float* __restrict__ x,
                       uint32_t* __restrict__ xh,
                       uint32_t* __restrict__ xl) {
    __shared__ uint32_t th[64][33];
    __shared__ uint32_t tl[64][33];
    const int t   = threadIdx.x;
    const int b   = blockIdx.z;
    const int cp0 = blockIdx.y * 64;
    const int p0  = blockIdx.x * 32;

#pragma unroll
    for (int it = 0; it < 8; it++) {
        int cp = it * 8 + (t >> 5);
        int p  = t & 31;
        const float* s = x + ((size_t)(b * CIN + 2 * (cp0 + cp))) * HW + p0 + p;
        float a = s[0];
        float c = s[HW];
        uint16_t ha, la, hc, lc;
        split_bf16(a, ha, la); split_bf16(c, hc, lc);
        th[cp][p] = pack2(ha, hc);
        tl[cp][p] = pack2(la, lc);
    }
    __syncthreads();

#pragma unroll
    for (int it = 0; it < 2; it++) {
        int idx = t + it * 256;
        int p   = idx >> 4;
        int c4  = (idx & 15) * 4;
        uint4 hv = make_uint4(th[c4][p], th[c4 + 1][p], th[c4 + 2][p], th[c4 + 3][p]);
        uint4 lv = make_uint4(tl[c4][p], tl[c4 + 1][p], tl[c4 + 2][p], tl[c4 + 3][p]);
        size_t o = ((size_t)b * HW + p0 + p) * KWX + cp0 + c4;
        *(uint4*)(xh + o) = hv;
        *(uint4*)(xl + o) = lv;
    }
}

// ===========================================================================
// tensor GEMM, 2-stage cp.async pipeline (SINGLE barrier per k-iter).
// ===========================================================================
#define STRIDE20 20
#define ST_AH 0
#define ST_AL 2560
#define ST_BH 5120
#define ST_BL 7680
#define ST_WORDS 10240
#define SMEM_BYTES (2 * ST_WORDS * 4)

__device__ __forceinline__ void stage_tile(uint32_t* sbase, int t, int KW,
                                           const uint32_t* ahr, const uint32_t* alr,
                                           const uint32_t* bhr, const uint32_t* blr) {
#pragma unroll
    for (int r = 0; r < 2; r++) {
        int id = t + r * 256, o = id >> 2, c4 = (id & 3) * 4;
        cpasync16(sbase + ST_AH + o * STRIDE20 + c4, ahr + (size_t)o * KW + c4);
        cpasync16(sbase + ST_AL + o * STRIDE20 + c4, alr + (size_t)o * KW + c4);
    }
#pragma unroll
    for (int r = 0; r < 2; r++) {
        int id = t + r * 256, n = id >> 2, c4 = (id & 3) * 4;
        cpasync16(sbase + ST_BH + n * STRIDE20 + c4, bhr + (size_t)n * KW + c4);
        cpasync16(sbase + ST_BL + n * STRIDE20 + c4, blr + (size_t)n * KW + c4);
    }
    asm volatile("cp.async.commit_group;" ::: "memory");
}

template <bool BN>
__global__ __launch_bounds__(256, 2)
void mma_gemm_kernel(const uint32_t* __restrict__ Bh_g,
                     const uint32_t* __restrict__ Bl_g,
                     const uint32_t* __restrict__ Ah_g,
                     const uint32_t* __restrict__ Al_g,
                     float* __restrict__ C, int K, int Ochan,
                     const float* __restrict__ bn_gamma,
                     const float* __restrict__ bn_beta,
                     const float* __restrict__ bn_mean,
                     const float* __restrict__ bn_var)
{
    extern __shared__ uint32_t smw[];
    const int KW = K >> 1;
    const int t = threadIdx.x, lane = t & 31, wid = t >> 5;
    const int wm = wid & 3, wn = wid >> 2;
    const int bx = blockIdx.x;
    const int b  = bx >> 5;
    const int p0 = (bx & 31) * 128;
    const int o0 = blockIdx.y * 128;

    const uint32_t* Bhb = Bh_g + ((size_t)b * HW + p0) * KW;
    const uint32_t* Blb = Bl_g + ((size_t)b * HW + p0) * KW;
    const uint32_t* Ahb = Ah_g + (size_t)o0 * KW;
    const uint32_t* Alb = Al_g + (size_t)o0 * KW;

    uint32_t aoff[2];
#pragma unroll
    for (int i = 0; i < 2; i++)
        aoff[i] = ((wm * 32 + i * 16 + (lane & 15)) * STRIDE20 +
                   ((lane >> 4) & 1) * 4) * 4;
    uint32_t boff[4];
#pragma unroll
    for (int jj = 0; jj < 4; jj++)
        boff[jj] = ((wn * 64 + jj * 16 + (lane & 7) + ((lane >> 4) & 1) * 8) * STRIDE20 +
                    ((lane >> 3) & 1) * 4) * 4;

    const uint32_t smem32 = (uint32_t)__cvta_generic_to_shared(smw);

    float acc[2][8][4];
#pragma unroll
    for (int i = 0; i < 2; i++)
#pragma unroll
        for (int j = 0; j < 8; j++)
#pragma unroll
            for (int e = 0; e < 4; e++) acc[i][j][e] = 0.f;

    const int NT = K / 32;
    stage_tile(smw, t, KW, Ahb, Alb, Bhb, Blb);   // stage 0 -> buf 0

    for (int kt = 0; kt < NT; kt++) {
        // stage kt is the only outstanding group here
        asm volatile("cp.async.wait_group 0;" ::: "memory");
        __syncthreads();   // orders compute(kt-1) of ALL warps before prefetch below

        if (kt + 1 < NT) {
            int kw0 = (kt + 1) * 16;
            stage_tile(smw + ((kt + 1) & 1) * ST_WORDS, t, KW,
                       Ahb + kw0, Alb + kw0, Bhb + kw0, Blb + kw0);
        }

        const uint32_t sb = smem32 + ((kt & 1) ? ST_WORDS * 4 : 0);

#pragma unroll
        for (int s = 0; s < 2; s++) {
            const uint32_t sd = s * 32;
            uint32_t ah[2][4], al[2][4], bb[4][4];
#pragma unroll
            for (int i = 0; i < 2; i++) {
                LDSM_X4(ah[i], sb + ST_AH * 4 + aoff[i] + sd);
                LDSM_X4(al[i], sb + ST_AL * 4 + aoff[i] + sd);
            }
#pragma unroll
            for (int jj = 0; jj < 4; jj++)
                LDSM_X4(bb[jj], sb + ST_BH * 4 + boff[jj] + sd);
#pragma unroll
            for (int jj = 0; jj < 4; jj++)
#pragma unroll
                for (int h = 0; h < 2; h++) {
                    int j = 2 * jj + h;
                    uint32_t b0 = bb[jj][2 * h], b1 = bb[jj][2 * h + 1];
#pragma unroll
                    for (int i = 0; i < 2; i++) {
                        mma_bf16(acc[i][j], ah[i], b0, b1);
                        mma_bf16(acc[i][j], al[i], b0, b1);
                    }
                }
#pragma unroll
            for (int jj = 0; jj < 4; jj++)
                LDSM_X4(bb[jj], sb + ST_BL * 4 + boff[jj] + sd);
#pragma unroll
            for (int jj = 0; jj < 4; jj++)
#pragma unroll
                for (int h = 0; h < 2; h++) {
                    int j = 2 * jj + h;
                    uint32_t b0 = bb[jj][2 * h], b1 = bb[jj][2 * h + 1];
#pragma unroll
                    for (int i = 0; i < 2; i++)
                        mma_bf16(acc[i][j], ah[i], b0, b1);
                }
        }
    }

    // ---- epilogue (optional fused BN affine) ----
    const int orow = o0 + wm * 32 + (lane >> 2);
    float scl[4], bia[4];
#pragma unroll
    for (int r = 0; r < 4; r++) {
        if (BN) {
            int o = orow + 8 * r;
            float inv = bn_gamma[o] * rsqrtf(bn_var[o] + BNEPS);
            scl[r] = inv;
            bia[r] = bn_beta[o] - bn_mean[o] * inv;
        } else { scl[r] = 1.f; bia[r] = 0.f; }
    }
    float* Cb = C + (size_t)b * Ochan * HW;
    const int pbase = p0 + wn * 64 + (lane & 3) * 2;
#pragma unroll
    for (int i = 0; i < 2; i++) {
        int oA = orow + 16 * i;
        int r0 = 2 * i;
#pragma unroll
        for (int j = 0; j < 8; j++) {
            int p = pbase + 8 * j;
            float2 v0, v1;
            v0.x = acc[i][j][0] * scl[r0] + bia[r0];
            v0.y = acc[i][j][1] * scl[r0] + bia[r0];
            v1.x = acc[i][j][2] * scl[r0 + 1] + bia[r0 + 1];
            v1.y = acc[i][j][3] * scl[r0 + 1] + bia[r0 + 1];
            *(float2*)&Cb[(size_t)oA * HW + p]       = v0;
            *(float2*)&Cb[(size_t)(oA + 8) * HW + p] = v1;
        }
    }
}

// ---------------------------------------------------------------------------
// Fused depthwise 5x5 + grouped 8x8 pointwise — register sliding window.
// Task = (channel, row, 8-col strip): 15 LDS.128 + 200 FMA per 8 outputs,
// dw results exchanged via smem for the pw mix. ~13x less smem traffic.
// ---------------------------------------------------------------------------
__global__ __launch_bounds__(256)
void dwpw_kernel(const float* __restrict__ w_dw,
                 const float* __restrict__ w_pw)
{
    const int b  = blockIdx.z;
    const int g  = blockIdx.y;
    const int r0 = blockIdx.x * 8;
    const int t  = threadIdx.x;

    __shared__ float sin_[8][12][68];
    __shared__ float sdw[8][8][68];
    __shared__ float swdw[8][25];
    __shared__ float swpw[64];

    const float* src = g_qkv + ((size_t)b * QKVCH + g * 8) * HW;
    float*       dst = g_agg + ((size_t)b * QKVCH + g * 8) * HW;

    if (t < 200) swdw[t / 25][t % 25] = w_dw[(size_t)(g * 8 + t / 25) * 25 + (t % 25)];
    if (t < 64)  swpw[t] = w_pw[(size_t)g * 64 + t];

    // load input tile + halo (zero-padded)
    for (int idx = t; idx < 8 * 12 * 68; idx += 256) {
        int i   = idx / (12 * 68);
        int rem = idx % (12 * 68);
        int rr  = rem / 68, cc = rem % 68;
        int gr  = r0 + rr - 2, gc = cc - 2;
        float v = 0.f;
        if (gr >= 0 && gr < HH && gc >= 0 && gc < WW)
            v = src[(size_t)i * HW + gr * WW + gc];
        sin_[i][rr][cc] = v;
    }
    __syncthreads();

    // conv phase: 512 tasks (i, rr, cs)
#pragma unroll
    for (int j = 0; j < 2; j++) {
        int task = t + j * 256;
        int cs = task & 7, rr = (task >> 3) & 7, i = task >> 6;
        float acc0[8];
#pragma unroll
        for (int k = 0; k < 8; k++) acc0[k] = 0.f;
#pragma unroll
        for (int dy = 0; dy < 5; dy++) {
            const float* row = &sin_[i][rr + dy][cs * 8];
            float rbuf[12];
            *(float4*)&rbuf[0] = *(const float4*)&row[0];
            *(float4*)&rbuf[4] = *(const float4*)&row[4];
            *(float4*)&rbuf[8] = *(const float4*)&row[8];
#pragma unroll
            for (int dx = 0; dx < 5; dx++) {
                float wv = swdw[i][dy * 5 + dx];
#pragma unroll
                for (int k = 0; k < 8; k++)
                    acc0[k] = fmaf(rbuf[k + dx], wv, acc0[k]);
            }
        }
        *(float4*)&sdw[i][rr][cs * 8]     = make_float4(acc0[0], acc0[1], acc0[2], acc0[3]);
        *(float4*)&sdw[i][rr][cs * 8 + 4] = make_float4(acc0[4], acc0[5], acc0[6], acc0[7]);
    }
    __syncthreads();

    // pw phase: 512 tasks (o, rr, cs)
#pragma unroll
    for (int j = 0; j < 2; j++) {
        int task = t + j * 256;
        int cs = task & 7, rr = (task >> 3) & 7, o = task >> 6;
        float acc0[8];
#pragma unroll
        for (int k = 0; k < 8; k++) acc0[k] = 0.f;
#pragma unroll
        for (int i = 0; i < 8; i++) {
            float wv = swpw[o * 8 + i];
            float rbuf[8];
            *(float4*)&rbuf[0] = *(const float4*)&sdw[i][rr][cs * 8];
            *(float4*)&rbuf[4] = *(const float4*)&sdw[i][rr][cs * 8 + 4];
#pragma unroll
            for (int k = 0; k < 8; k++)
                acc0[k] = fmaf(rbuf[k], wv, acc0[k]);
        }
        float* dp = dst + (size_t)o * HW + (r0 + rr) * WW + cs * 8;
        *(float4*)&dp[0] = make_float4(acc0[0], acc0[1], acc0[2], acc0[3]);
        *(float4*)&dp[4] = make_float4(acc0[4], acc0[5], acc0[6], acc0[7]);
    }
}

// ---------------------------------------------------------------------------
// Linear attention per (batch, head); writes packed bf16 hi/lo, pixel-major.
// ---------------------------------------------------------------------------
__global__ __launch_bounds__(256)
void attn_kernel()
{
    const int b = blockIdx.y;
    const int h = blockIdx.x;
    const int t = threadIdx.x;

    const float* base = (h < 64)
        ? g_qkv + ((size_t)b * QKVCH + h * 24) * HW
        : g_agg + ((size_t)b * QKVCH + (h - 64) * 24) * HW;

    float kv[72];
#pragma unroll
    for (int i = 0; i < 72; i++) kv[i] = 0.f;

    for (int p = t; p < HW; p += 256) {
        float kd[8], ve[8];
#pragma unroll
        for (int d = 0; d < 8; d++) kd[d] = fmaxf(base[(size_t)(8 + d) * HW + p], 0.f);
#pragma unroll
        for (int e = 0; e < 8; e++) ve[e] = base[(size_t)(16 + e) * HW + p];
#pragma unroll
        for (int d = 0; d < 8; d++) {
#pragma unroll
            for (int e = 0; e < 8; e++) kv[d * 9 + e] = fmaf(kd[d], ve[e], kv[d * 9 + e]);
            kv[d * 9 + 8] += kd[d];
        }
    }

    __shared__ float red[8][72];
    __shared__ float kvf[72];
#pragma unroll
    for (int i = 0; i < 72; i++) {
        float v = kv[i];
        v += __shfl_xor_sync(0xffffffffu, v, 16);
        v += __shfl_xor_sync(0xffffffffu, v, 8);
        v += __shfl_xor_sync(0xffffffffu, v, 4);
        v += __shfl_xor_sync(0xffffffffu, v, 2);
        v += __shfl_xor_sync(0xffffffffu, v, 1);
        kv[i] = v;
    }
    const int lane = t & 31, wid = t >> 5;
    if (lane == 0) {
#pragma unroll
        for (int i = 0; i < 72; i++) red[wid][i] = kv[i];
    }
    __syncthreads();
    if (t < 72) {
        float s = 0.f;
#pragma unroll
        for (int w = 0; w < 8; w++) s += red[w][t];
        kvf[t] = s;
    }
    __syncthreads();

    uint32_t* dsth = g_atth + (size_t)b * HW * KWA + h * 4;
    uint32_t* dstl = g_attl + (size_t)b * HW * KWA + h * 4;
    for (int p = t; p < HW; p += 256) {
        float qd[8];
#pragma unroll
        for (int d = 0; d < 8; d++) qd[d] = fmaxf(base[(size_t)d * HW + p], 0.f);
        float num[9];
#pragma unroll
        for (int e = 0; e < 9; e++) {
            float s = 0.f;
#pragma unroll
            for (int d = 0; d < 8; d++) s = fmaf(qd[d], kvf[d * 9 + e], s);
            num[e] = s;
        }
        float inv = 1.f / (num[8] + EPSV);
        uint32_t hw4[4], lw4[4];
#pragma unroll
        for (int j = 0; j < 4; j++) {
            uint16_t h0, l0, h1, l1;
            split_bf16(num[2 * j] * inv, h0, l0);
            split_bf16(num[2 * j + 1] * inv, h1, l1);
            hw4[j] = pack2(h0, h1);
            lw4[j] = pack2(l0, l1);
        }
        *(uint4*)(dsth + (size_t)p * KWA) = make_uint4(hw4[0], hw4[1], hw4[2], hw4[3]);
        *(uint4*)(dstl + (size_t)p * KWA) = make_uint4(lw4[0], lw4[1], lw4[2], lw4[3]);
    }
}

// ---------------------------------------------------------------------------
extern "C" void kernel_launch(void* const* d_in, const int* in_sizes, int n_in,
                              void* d_out, int out_size)
{
    const float* x       = (const float*)d_in[0];
    const float* w_qkv   = (const float*)d_in[1];
    const float* w_dw    = (const float*)d_in[2];
    const float* w_pw    = (const float*)d_in[3];
    const float* w_proj  = (const float*)d_in[4];
    const float* bn_g    = (const float*)d_in[5];
    const float* bn_b    = (const float*)d_in[6];
    const float* bn_m    = (const float*)d_in[7];
    const float* bn_v    = (const float*)d_in[8];
    float* out = (float*)d_out;

    float *qkv_p;
    uint32_t *xh_p, *xl_p, *ath_p, *atl_p, *wqh_p, *wql_p, *wph_p, *wpl_p;
    cudaGetSymbolAddress((void**)&qkv_p, g_qkv);
    cudaGetSymbolAddress((void**)&xh_p,  g_xh);
    cudaGetSymbolAddress((void**)&xl_p,  g_xl);
    cudaGetSymbolAddress((void**)&ath_p, g_atth);
    cudaGetSymbolAddress((void**)&atl_p, g_attl);
    cudaGetSymbolAddress((void**)&wqh_p, g_wqh);
    cudaGetSymbolAddress((void**)&wql_p, g_wql);
    cudaGetSymbolAddress((void**)&wph_p, g_wph);
    cudaGetSymbolAddress((void**)&wpl_p, g_wpl);

    cudaFuncSetAttribute(mma_gemm_kernel<false>,
                         cudaFuncAttributeMaxDynamicSharedMemorySize, SMEM_BYTES);
    cudaFuncSetAttribute(mma_gemm_kernel<true>,
                         cudaFuncAttributeMaxDynamicSharedMemorySize, SMEM_BYTES);

    // 0) pre-split weights + x (x transposed to pixel-major)
    presplit_w_kernel<<<(QKVCH * KWX + 255) / 256, 256>>>(
        w_qkv, wqh_p, wql_p, QKVCH * KWX);
    presplit_w_kernel<<<(CIN * KWA + 255) / 256, 256>>>(
        w_proj, wph_p, wpl_p, CIN * KWA);
    presplit_x_kernel<<<dim3(HW / 32, CIN / 128, NB), 256>>>(x, xh_p, xl_p);

    // 1) qkv = x @ w_qkv   (K=512, O=1536)
    mma_gemm_kernel<false><<<dim3(128, QKVCH / 128), 256, SMEM_BYTES>>>(
        xh_p, xl_p, wqh_p, wql_p, qkv_p, CIN, QKVCH,
        nullptr, nullptr, nullptr, nullptr);

    // 2) depthwise 5x5 + grouped pointwise 8x8 (register sliding window)
    dwpw_kernel<<<dim3(HH / 8, NGROUP, NB), 256>>>(w_dw, w_pw);

    // 3) linear attention (128 heads) -> packed bf16 hi/lo, pixel-major
    attn_kernel<<<dim3(NHEAD, NB), 256>>>();

    // 4) proj GEMM (K=1024, O=512) + BN affine
    mma_gemm_kernel<true><<<dim3(128, CIN / 128), 256, SMEM_BYTES>>>(
        ath_p, atl_p, wph_p, wpl_p, out, ATTNCH, CIN,
        bn_g, bn_b, bn_m, bn_v);
}